// round 1
// baseline (speedup 1.0000x reference)
#include <cuda_runtime.h>
#include <cstddef>

#define NN 50000
#define DD 128

// Scratch: static device globals (allocation-free rule).
__device__ float g_buf0[NN * DD];
__device__ float g_buf1[NN * DD];
__device__ float g_agg[NN * DD];

// ---------------------------------------------------------------------------
// Zero kernel (agg must be cleared before each scatter)
// ---------------------------------------------------------------------------
__global__ void zero_kernel(float4* __restrict__ p, int n4) {
    int i = blockIdx.x * blockDim.x + threadIdx.x;
    if (i < n4) p[i] = make_float4(0.f, 0.f, 0.f, 0.f);
}

// ---------------------------------------------------------------------------
// Scatter: one warp per edge. agg[dst] += ew * h[src]
// Row is 128 floats = 32 float4 -> one float4 per lane.
// ---------------------------------------------------------------------------
__global__ void scatter_kernel(const float* __restrict__ x,
                               const int* __restrict__ ei,   // [2, E]
                               const float* __restrict__ ew,
                               float* __restrict__ agg, int E) {
    int gid  = blockIdx.x * blockDim.x + threadIdx.x;
    int e    = gid >> 5;
    int lane = gid & 31;
    if (e >= E) return;
    int s   = ei[e];
    int d   = ei[E + e];
    float w = ew[e];
    float4 v = ((const float4*)(x + (size_t)s * DD))[lane];
    float* ar = agg + (size_t)d * DD + lane * 4;
    atomicAdd(ar + 0, v.x * w);
    atomicAdd(ar + 1, v.y * w);
    atomicAdd(ar + 2, v.z * w);
    atomicAdd(ar + 3, v.w * w);
}

// ---------------------------------------------------------------------------
// Fused GEMM: out = act( agg @ Wrel + h @ Wroot + bias )
// Treated as one GEMM with K = 256 (first 128 from agg/Wrel, next 128 from
// h/Wroot). BM=128, BN=128, BK=16, 256 threads, 8x8 micro-tile per thread.
// ---------------------------------------------------------------------------
template <bool RELU>
__global__ void __launch_bounds__(256, 2)
gemm_fused(const float* __restrict__ Aagg, const float* __restrict__ Ah,
           const float* __restrict__ Wrel, const float* __restrict__ Wroot,
           const float* __restrict__ bias, float* __restrict__ out, int n) {
    __shared__ float As[16][128];   // transposed A tile: As[k][m]
    __shared__ float Bs[16][128];   // Bs[k][j]

    const int tid  = threadIdx.x;
    const int tx   = tid & 15;      // output col group: cols tx*8 .. tx*8+7
    const int ty   = tid >> 4;      // output row group: rows ty*8 .. ty*8+7
    const int row0 = blockIdx.x * 128;

    float acc[8][8];
#pragma unroll
    for (int i = 0; i < 8; i++)
#pragma unroll
        for (int j = 0; j < 8; j++) acc[i][j] = 0.f;

    const int la = tid * 2;  // two float4 loads each for A and B tiles

    for (int kk = 0; kk < 256; kk += 16) {
        const float* A = (kk < 128) ? Aagg : Ah;
        const float* W = (kk < 128) ? Wrel : Wroot;
        const int k0 = kk & 127;

        // Load A tile: 128 rows x 16 k-cols = 512 float4
#pragma unroll
        for (int i = 0; i < 2; i++) {
            int li = la + i;
            int r  = li >> 2;
            int c4 = (li & 3) * 4;
            int gr = row0 + r;
            float4 v = make_float4(0.f, 0.f, 0.f, 0.f);
            if (gr < n) v = *(const float4*)(A + (size_t)gr * DD + k0 + c4);
            As[c4 + 0][r] = v.x;
            As[c4 + 1][r] = v.y;
            As[c4 + 2][r] = v.z;
            As[c4 + 3][r] = v.w;
        }
        // Load B tile: 16 k-rows x 128 cols = 512 float4
#pragma unroll
        for (int i = 0; i < 2; i++) {
            int li = la + i;
            int kr = li >> 5;
            int c4 = (li & 31) * 4;
            *(float4*)&Bs[kr][c4] = *(const float4*)(W + (size_t)(k0 + kr) * DD + c4);
        }
        __syncthreads();

#pragma unroll
        for (int k = 0; k < 16; k++) {
            float a[8], b[8];
            *(float4*)&a[0] = *(const float4*)&As[k][ty * 8];
            *(float4*)&a[4] = *(const float4*)&As[k][ty * 8 + 4];
            *(float4*)&b[0] = *(const float4*)&Bs[k][tx * 8];
            *(float4*)&b[4] = *(const float4*)&Bs[k][tx * 8 + 4];
#pragma unroll
            for (int m = 0; m < 8; m++)
#pragma unroll
                for (int q = 0; q < 8; q++) acc[m][q] += a[m] * b[q];
        }
        __syncthreads();
    }

    // Epilogue: bias + optional relu + store
    float bv[8];
    *(float4*)&bv[0] = *(const float4*)&bias[tx * 8];
    *(float4*)&bv[4] = *(const float4*)&bias[tx * 8 + 4];

#pragma unroll
    for (int m = 0; m < 8; m++) {
        int gr = row0 + ty * 8 + m;
        if (gr >= n) continue;
        float o[8];
#pragma unroll
        for (int q = 0; q < 8; q++) {
            float v = acc[m][q] + bv[q];
            o[q] = RELU ? fmaxf(v, 0.f) : v;
        }
        *(float4*)(out + (size_t)gr * DD + tx * 8)     = *(float4*)&o[0];
        *(float4*)(out + (size_t)gr * DD + tx * 8 + 4) = *(float4*)&o[4];
    }
}

// ---------------------------------------------------------------------------
// Launch
// ---------------------------------------------------------------------------
extern "C" void kernel_launch(void* const* d_in, const int* in_sizes, int n_in,
                              void* d_out, int out_size) {
    const float* x   = (const float*)d_in[0];
    const int*   ei  = (const int*)d_in[1];
    const float* ea  = (const float*)d_in[2];
    const float* wr0 = (const float*)d_in[3];
    const float* br0 = (const float*)d_in[4];
    const float* wo0 = (const float*)d_in[5];
    const float* wr1 = (const float*)d_in[6];
    const float* br1 = (const float*)d_in[7];
    const float* wo1 = (const float*)d_in[8];
    const float* wr2 = (const float*)d_in[9];
    const float* br2 = (const float*)d_in[10];
    const float* wo2 = (const float*)d_in[11];
    float* out = (float*)d_out;

    const int n = in_sizes[0] / DD;   // 50000
    const int E = in_sizes[2];        // 800000

    float *buf0, *buf1, *agg;
    cudaGetSymbolAddress((void**)&buf0, g_buf0);
    cudaGetSymbolAddress((void**)&buf1, g_buf1);
    cudaGetSymbolAddress((void**)&agg,  g_agg);

    const int n4       = n * DD / 4;
    const int zb       = (n4 + 255) / 256;
    const int sb       = (E * 32 + 255) / 256;
    const int gb       = (n + 127) / 128;

    // Layer 0: h = x -> buf0 (relu)
    zero_kernel<<<zb, 256>>>((float4*)agg, n4);
    scatter_kernel<<<sb, 256>>>(x, ei, ea, agg, E);
    gemm_fused<true><<<gb, 256>>>(agg, x, wr0, wo0, br0, buf0, n);

    // Layer 1: buf0 -> buf1 (relu)
    zero_kernel<<<zb, 256>>>((float4*)agg, n4);
    scatter_kernel<<<sb, 256>>>(buf0, ei, ea, agg, E);
    gemm_fused<true><<<gb, 256>>>(agg, buf0, wr1, wo1, br1, buf1, n);

    // Layer 2: buf1 -> out (no relu)
    zero_kernel<<<zb, 256>>>((float4*)agg, n4);
    scatter_kernel<<<sb, 256>>>(buf1, ei, ea, agg, E);
    gemm_fused<false><<<gb, 256>>>(agg, buf1, wr2, wo2, br2, out, n);
}

// round 2
// speedup vs baseline: 1.8990x; 1.8990x over previous
#include <cuda_runtime.h>
#include <cuda_bf16.h>
#include <cstdint>
#include <cstddef>

#define NN 50000
#define DD 128
#define NLAYERS 3

// Scratch (allocation-free rule: device globals)
__device__ float g_buf0[NN * DD];
__device__ float g_buf1[NN * DD];
__device__ float g_agg[NN * DD];
// Pre-split, pre-transposed weights: [layer][n=128][k=256], bf16 hi/lo planes
__device__ __nv_bfloat16 g_whi[NLAYERS * DD * 256];
__device__ __nv_bfloat16 g_wlo[NLAYERS * DD * 256];

// ---------------------------------------------------------------------------
// Zero kernel
// ---------------------------------------------------------------------------
__global__ void zero_kernel(float4* __restrict__ p, int n4) {
    int i = blockIdx.x * blockDim.x + threadIdx.x;
    if (i < n4) p[i] = make_float4(0.f, 0.f, 0.f, 0.f);
}

// ---------------------------------------------------------------------------
// Weight prep: W = [Wrel; Wroot] (K=256), stored transposed [n][k] and split
// into bf16 hi + lo planes.
// ---------------------------------------------------------------------------
__global__ void prep_w(const float* __restrict__ wrel,
                       const float* __restrict__ wroot,
                       __nv_bfloat16* __restrict__ whi,
                       __nv_bfloat16* __restrict__ wlo) {
    int i = blockIdx.x * blockDim.x + threadIdx.x;
    if (i >= DD * 256) return;
    int n = i >> 8;          // 0..127
    int k = i & 255;         // 0..255
    float v = (k < 128) ? wrel[k * DD + n] : wroot[(k - 128) * DD + n];
    __nv_bfloat16 h = __float2bfloat16(v);
    float lo = v - __bfloat162float(h);
    whi[n * 256 + k] = h;
    wlo[n * 256 + k] = __float2bfloat16(lo);
}

// ---------------------------------------------------------------------------
// Scatter: one warp per edge, vectorized 16B global reduction.
// ---------------------------------------------------------------------------
__global__ void scatter_kernel(const float* __restrict__ x,
                               const int* __restrict__ ei,
                               const float* __restrict__ ew,
                               float* __restrict__ agg, int E) {
    int gid  = blockIdx.x * blockDim.x + threadIdx.x;
    int e    = gid >> 5;
    int lane = gid & 31;
    if (e >= E) return;
    int s   = ei[e];
    int d   = ei[E + e];
    float w = ew[e];
    float4 v = ((const float4*)(x + (size_t)s * DD))[lane];
    float* p = agg + (size_t)d * DD + lane * 4;
    asm volatile("red.global.add.v4.f32 [%0], {%1,%2,%3,%4};"
                 :: "l"(p), "f"(v.x * w), "f"(v.y * w), "f"(v.z * w), "f"(v.w * w)
                 : "memory");
}

// ---------------------------------------------------------------------------
// Tensor-core GEMM: out = act( [agg|h] @ [Wrel;Wroot] + bias )
// bf16 3-term split (hi*hi + hi*lo + lo*hi) on mma.sync.m16n8k16, fp32 accum.
// Block tile 128x128, K=256 in 16 steps of 16. 8 warps as 2(m) x 4(n),
// warp tile 64x32 -> 4 m-tiles x 4 n-tiles of m16n8 per warp.
// ---------------------------------------------------------------------------
#define MMA_BF16(acc, a, b)                                                    \
    asm volatile(                                                              \
        "mma.sync.aligned.m16n8k16.row.col.f32.bf16.bf16.f32 "                 \
        "{%0,%1,%2,%3}, {%4,%5,%6,%7}, {%8,%9}, {%0,%1,%2,%3};"                \
        : "+f"(acc[0]), "+f"(acc[1]), "+f"(acc[2]), "+f"(acc[3])               \
        : "r"(a[0]), "r"(a[1]), "r"(a[2]), "r"(a[3]), "r"(b[0]), "r"(b[1]))

__device__ __forceinline__ uint32_t pack_bf16(__nv_bfloat16 a, __nv_bfloat16 b) {
    __nv_bfloat162 t; t.x = a; t.y = b;   // .x in low 16 bits
    return *reinterpret_cast<uint32_t*>(&t);
}

template <bool RELU>
__global__ void __launch_bounds__(256, 1)
gemm_mma(const float* __restrict__ Aagg, const float* __restrict__ Ah,
         const __nv_bfloat16* __restrict__ Whi, const __nv_bfloat16* __restrict__ Wlo,
         const float* __restrict__ bias, float* __restrict__ out, int n) {
    // Each plane: 128 rows x 8 words (16 bf16) with xor swizzle word' = w ^ (row&7)
    __shared__ uint32_t As_hi[128 * 8];
    __shared__ uint32_t As_lo[128 * 8];
    __shared__ uint32_t Bs_hi[128 * 8];
    __shared__ uint32_t Bs_lo[128 * 8];

    const int tid  = threadIdx.x;
    const int lane = tid & 31;
    const int wid  = tid >> 5;
    const int wm   = wid >> 2;       // 0..1
    const int wn   = wid & 3;        // 0..3
    const int row0 = blockIdx.x * 128;
    const int r    = lane >> 2;      // 0..7
    const int c    = lane & 3;       // 0..3

    const int lrow  = tid >> 1;      // 0..127 (tile row this thread loads)
    const int lhalf = tid & 1;       // k-halves 0..7 / 8..15

    float acc[4][4][4];
#pragma unroll
    for (int mt = 0; mt < 4; mt++)
#pragma unroll
        for (int nt = 0; nt < 4; nt++)
#pragma unroll
            for (int q = 0; q < 4; q++) acc[mt][nt][q] = 0.f;

    for (int kk = 0; kk < 16; kk++) {
        const int k0 = kk * 16;
        const float* A = (kk < 8) ? Aagg : Ah;
        const int ka = k0 & 127;

        // ---- A tile load + fp32 -> bf16 hi/lo split ----
        {
            int gr = row0 + lrow;
            float vv[8];
            if (gr < n) {
                const float* ap = A + (size_t)gr * DD + ka + 8 * lhalf;
                float4 v0 = *(const float4*)ap;
                float4 v1 = *(const float4*)(ap + 4);
                vv[0]=v0.x; vv[1]=v0.y; vv[2]=v0.z; vv[3]=v0.w;
                vv[4]=v1.x; vv[5]=v1.y; vv[6]=v1.z; vv[7]=v1.w;
            } else {
#pragma unroll
                for (int j = 0; j < 8; j++) vv[j] = 0.f;
            }
#pragma unroll
            for (int j = 0; j < 4; j++) {
                float a0 = vv[2*j], a1 = vv[2*j+1];
                __nv_bfloat16 h0 = __float2bfloat16(a0);
                __nv_bfloat16 h1 = __float2bfloat16(a1);
                float l0 = a0 - __bfloat162float(h0);
                float l1 = a1 - __bfloat162float(h1);
                int w   = 4 * lhalf + j;
                int idx = lrow * 8 + (w ^ (lrow & 7));
                As_hi[idx] = pack_bf16(h0, h1);
                As_lo[idx] = pack_bf16(__float2bfloat16(l0), __float2bfloat16(l1));
            }
        }
        // ---- B tile copy (already bf16, layout [n][256]) ----
        {
            const uint4 hv = *(const uint4*)(Whi + (size_t)lrow * 256 + k0 + 8 * lhalf);
            const uint4 lv = *(const uint4*)(Wlo + (size_t)lrow * 256 + k0 + 8 * lhalf);
            uint32_t hw[4] = {hv.x, hv.y, hv.z, hv.w};
            uint32_t lw[4] = {lv.x, lv.y, lv.z, lv.w};
#pragma unroll
            for (int j = 0; j < 4; j++) {
                int w   = 4 * lhalf + j;
                int idx = lrow * 8 + (w ^ (lrow & 7));
                Bs_hi[idx] = hw[j];
                Bs_lo[idx] = lw[j];
            }
        }
        __syncthreads();

        // ---- fragments ----
        uint32_t afh[4][4], afl[4][4], bfh[4][2], bfl[4][2];
#pragma unroll
        for (int mt = 0; mt < 4; mt++) {
            int mr0 = wm * 64 + mt * 16 + r;
            int mr1 = mr0 + 8;
            afh[mt][0] = As_hi[mr0 * 8 + ( c      ^ (mr0 & 7))];
            afh[mt][1] = As_hi[mr1 * 8 + ( c      ^ (mr1 & 7))];
            afh[mt][2] = As_hi[mr0 * 8 + ((c + 4) ^ (mr0 & 7))];
            afh[mt][3] = As_hi[mr1 * 8 + ((c + 4) ^ (mr1 & 7))];
            afl[mt][0] = As_lo[mr0 * 8 + ( c      ^ (mr0 & 7))];
            afl[mt][1] = As_lo[mr1 * 8 + ( c      ^ (mr1 & 7))];
            afl[mt][2] = As_lo[mr0 * 8 + ((c + 4) ^ (mr0 & 7))];
            afl[mt][3] = As_lo[mr1 * 8 + ((c + 4) ^ (mr1 & 7))];
        }
#pragma unroll
        for (int nt = 0; nt < 4; nt++) {
            int nr = wn * 32 + nt * 8 + r;
            bfh[nt][0] = Bs_hi[nr * 8 + ( c      ^ (nr & 7))];
            bfh[nt][1] = Bs_hi[nr * 8 + ((c + 4) ^ (nr & 7))];
            bfl[nt][0] = Bs_lo[nr * 8 + ( c      ^ (nr & 7))];
            bfl[nt][1] = Bs_lo[nr * 8 + ((c + 4) ^ (nr & 7))];
        }

#pragma unroll
        for (int mt = 0; mt < 4; mt++)
#pragma unroll
            for (int nt = 0; nt < 4; nt++) {
                MMA_BF16(acc[mt][nt], afh[mt], bfh[nt]);
                MMA_BF16(acc[mt][nt], afh[mt], bfl[nt]);
                MMA_BF16(acc[mt][nt], afl[mt], bfh[nt]);
            }
        __syncthreads();
    }

    // ---- epilogue: bias + relu + store ----
#pragma unroll
    for (int nt = 0; nt < 4; nt++) {
        int col = wn * 32 + nt * 8 + 2 * c;
        float b0 = bias[col], b1 = bias[col + 1];
#pragma unroll
        for (int mt = 0; mt < 4; mt++) {
            int g0 = row0 + wm * 64 + mt * 16 + r;
            int g1 = g0 + 8;
            float v0 = acc[mt][nt][0] + b0;
            float v1 = acc[mt][nt][1] + b1;
            float v2 = acc[mt][nt][2] + b0;
            float v3 = acc[mt][nt][3] + b1;
            if (RELU) {
                v0 = fmaxf(v0, 0.f); v1 = fmaxf(v1, 0.f);
                v2 = fmaxf(v2, 0.f); v3 = fmaxf(v3, 0.f);
            }
            if (g0 < n) *(float2*)(out + (size_t)g0 * DD + col) = make_float2(v0, v1);
            if (g1 < n) *(float2*)(out + (size_t)g1 * DD + col) = make_float2(v2, v3);
        }
    }
}

// ---------------------------------------------------------------------------
// Launch
// ---------------------------------------------------------------------------
extern "C" void kernel_launch(void* const* d_in, const int* in_sizes, int n_in,
                              void* d_out, int out_size) {
    const float* x   = (const float*)d_in[0];
    const int*   ei  = (const int*)d_in[1];
    const float* ea  = (const float*)d_in[2];
    const float* wr[3] = {(const float*)d_in[3], (const float*)d_in[6], (const float*)d_in[9]};
    const float* br[3] = {(const float*)d_in[4], (const float*)d_in[7], (const float*)d_in[10]};
    const float* wo[3] = {(const float*)d_in[5], (const float*)d_in[8], (const float*)d_in[11]};
    float* out = (float*)d_out;

    const int n = in_sizes[0] / DD;   // 50000
    const int E = in_sizes[2];        // 800000

    float *buf0, *buf1, *agg;
    __nv_bfloat16 *whi, *wlo;
    cudaGetSymbolAddress((void**)&buf0, g_buf0);
    cudaGetSymbolAddress((void**)&buf1, g_buf1);
    cudaGetSymbolAddress((void**)&agg,  g_agg);
    cudaGetSymbolAddress((void**)&whi,  g_whi);
    cudaGetSymbolAddress((void**)&wlo,  g_wlo);

    const int n4 = n * DD / 4;
    const int zb = (n4 + 255) / 256;
    const int sb = (E * 32 + 255) / 256;
    const int gb = (n + 127) / 128;
    const int pb = (DD * 256 + 255) / 256;

    // Weight prep (deterministic, every call)
    for (int l = 0; l < 3; l++)
        prep_w<<<pb, 256>>>(wr[l], wo[l], whi + (size_t)l * DD * 256,
                            wlo + (size_t)l * DD * 256);

    // Layer 0: x -> buf0 (relu)
    zero_kernel<<<zb, 256>>>((float4*)agg, n4);
    scatter_kernel<<<sb, 256>>>(x, ei, ea, agg, E);
    gemm_mma<true><<<gb, 256>>>(agg, x, whi, wlo, br[0], buf0, n);

    // Layer 1: buf0 -> buf1 (relu)
    zero_kernel<<<zb, 256>>>((float4*)agg, n4);
    scatter_kernel<<<sb, 256>>>(buf0, ei, ea, agg, E);
    gemm_mma<true><<<gb, 256>>>(agg, buf0, whi + (size_t)DD * 256,
                                wlo + (size_t)DD * 256, br[1], buf1, n);

    // Layer 2: buf1 -> out (no relu)
    zero_kernel<<<zb, 256>>>((float4*)agg, n4);
    scatter_kernel<<<sb, 256>>>(buf1, ei, ea, agg, E);
    gemm_mma<false><<<gb, 256>>>(agg, buf1, whi + (size_t)2 * DD * 256,
                                 wlo + (size_t)2 * DD * 256, br[2], out, n);
}

// round 3
// speedup vs baseline: 2.3064x; 1.2145x over previous
#include <cuda_runtime.h>
#include <cuda_bf16.h>
#include <cstdint>
#include <cstddef>

#define NN 50000
#define EE 800000
#define DD 128
#define NLAYERS 3

// Scratch (allocation-free rule: device globals)
__device__ float g_buf0[NN * DD];
__device__ float g_buf1[NN * DD];
__device__ float g_agg[NN * DD];
__device__ __nv_bfloat16 g_whi[NLAYERS * DD * 256];
__device__ __nv_bfloat16 g_wlo[NLAYERS * DD * 256];
// CSR (built once per call, reused by all 3 layers)
__device__ int   g_deg[NN];
__device__ int   g_rowptr[NN + 1];
__device__ int   g_cursor[NN];
__device__ int   g_esrc[EE];
__device__ float g_ews[EE];

// ---------------------------------------------------------------------------
// CSR build
// ---------------------------------------------------------------------------
__global__ void zero_deg(int* __restrict__ deg, int n) {
    int i = blockIdx.x * blockDim.x + threadIdx.x;
    if (i < n) deg[i] = 0;
}

__global__ void hist_kernel(const int* __restrict__ ei, int* __restrict__ deg, int E) {
    int e = blockIdx.x * blockDim.x + threadIdx.x;
    if (e < E) atomicAdd(&deg[ei[E + e]], 1);
}

// One-block exclusive scan over NN degrees -> rowptr (also inits cursor).
__global__ void __launch_bounds__(1024)
scan_kernel(const int* __restrict__ deg, int* __restrict__ rowptr,
            int* __restrict__ cursor, int n) {
    __shared__ int s[1024];
    const int t = threadIdx.x;
    const int C = (n + 1023) / 1024;
    const int beg = t * C;
    const int end = min(beg + C, n);
    int local = 0;
    for (int i = beg; i < end; i++) local += deg[i];
    s[t] = local;
    __syncthreads();
    // Hillis-Steele inclusive scan over 1024 partials
    for (int off = 1; off < 1024; off <<= 1) {
        int v = (t >= off) ? s[t - off] : 0;
        __syncthreads();
        s[t] += v;
        __syncthreads();
    }
    int run = s[t] - local;   // exclusive prefix of this chunk
    for (int i = beg; i < end; i++) {
        rowptr[i] = run;
        cursor[i] = run;
        run += deg[i];
    }
    if (t == 1023) rowptr[n] = s[1023];
}

__global__ void fill_kernel(const int* __restrict__ ei, const float* __restrict__ ew,
                            int* __restrict__ cursor,
                            int* __restrict__ esrc, float* __restrict__ ews, int E) {
    int e = blockIdx.x * blockDim.x + threadIdx.x;
    if (e >= E) return;
    int d = ei[E + e];
    int pos = atomicAdd(&cursor[d], 1);
    esrc[pos] = ei[e];
    ews[pos]  = ew[e];
}

// ---------------------------------------------------------------------------
// Gather: one warp per node, register accumulation. No atomics, no zeroing.
// ---------------------------------------------------------------------------
__global__ void __launch_bounds__(512)
gather_csr(const float* __restrict__ x, const int* __restrict__ rowptr,
           const int* __restrict__ esrc, const float* __restrict__ ews,
           float* __restrict__ agg, int n) {
    int warp = (blockIdx.x * blockDim.x + threadIdx.x) >> 5;
    int lane = threadIdx.x & 31;
    if (warp >= n) return;
    int i   = rowptr[warp];
    int end = rowptr[warp + 1];
    float4 acc0 = make_float4(0.f, 0.f, 0.f, 0.f);
    float4 acc1 = make_float4(0.f, 0.f, 0.f, 0.f);
    for (; i + 1 < end; i += 2) {
        int   s0 = esrc[i],     s1 = esrc[i + 1];
        float w0 = ews[i],      w1 = ews[i + 1];
        float4 v0 = __ldg((const float4*)(x + (size_t)s0 * DD) + lane);
        float4 v1 = __ldg((const float4*)(x + (size_t)s1 * DD) + lane);
        acc0.x += v0.x * w0; acc0.y += v0.y * w0; acc0.z += v0.z * w0; acc0.w += v0.w * w0;
        acc1.x += v1.x * w1; acc1.y += v1.y * w1; acc1.z += v1.z * w1; acc1.w += v1.w * w1;
    }
    if (i < end) {
        int   s0 = esrc[i];
        float w0 = ews[i];
        float4 v0 = __ldg((const float4*)(x + (size_t)s0 * DD) + lane);
        acc0.x += v0.x * w0; acc0.y += v0.y * w0; acc0.z += v0.z * w0; acc0.w += v0.w * w0;
    }
    acc0.x += acc1.x; acc0.y += acc1.y; acc0.z += acc1.z; acc0.w += acc1.w;
    ((float4*)(agg + (size_t)warp * DD))[lane] = acc0;
}

// ---------------------------------------------------------------------------
// Weight prep: W = [Wrel; Wroot] transposed [n][k=256], bf16 hi/lo split.
// ---------------------------------------------------------------------------
__global__ void prep_w(const float* __restrict__ wrel,
                       const float* __restrict__ wroot,
                       __nv_bfloat16* __restrict__ whi,
                       __nv_bfloat16* __restrict__ wlo) {
    int i = blockIdx.x * blockDim.x + threadIdx.x;
    if (i >= DD * 256) return;
    int n = i >> 8;
    int k = i & 255;
    float v = (k < 128) ? wrel[k * DD + n] : wroot[(k - 128) * DD + n];
    __nv_bfloat16 h = __float2bfloat16(v);
    float lo = v - __bfloat162float(h);
    whi[n * 256 + k] = h;
    wlo[n * 256 + k] = __float2bfloat16(lo);
}

// ---------------------------------------------------------------------------
// Tensor-core GEMM: out = act( [agg|h] @ [Wrel;Wroot] + bias )  (unchanged)
// ---------------------------------------------------------------------------
#define MMA_BF16(acc, a, b)                                                    \
    asm volatile(                                                              \
        "mma.sync.aligned.m16n8k16.row.col.f32.bf16.bf16.f32 "                 \
        "{%0,%1,%2,%3}, {%4,%5,%6,%7}, {%8,%9}, {%0,%1,%2,%3};"                \
        : "+f"(acc[0]), "+f"(acc[1]), "+f"(acc[2]), "+f"(acc[3])               \
        : "r"(a[0]), "r"(a[1]), "r"(a[2]), "r"(a[3]), "r"(b[0]), "r"(b[1]))

__device__ __forceinline__ uint32_t pack_bf16(__nv_bfloat16 a, __nv_bfloat16 b) {
    __nv_bfloat162 t; t.x = a; t.y = b;
    return *reinterpret_cast<uint32_t*>(&t);
}

template <bool RELU>
__global__ void __launch_bounds__(256, 1)
gemm_mma(const float* __restrict__ Aagg, const float* __restrict__ Ah,
         const __nv_bfloat16* __restrict__ Whi, const __nv_bfloat16* __restrict__ Wlo,
         const float* __restrict__ bias, float* __restrict__ out, int n) {
    __shared__ uint32_t As_hi[128 * 8];
    __shared__ uint32_t As_lo[128 * 8];
    __shared__ uint32_t Bs_hi[128 * 8];
    __shared__ uint32_t Bs_lo[128 * 8];

    const int tid  = threadIdx.x;
    const int lane = tid & 31;
    const int wid  = tid >> 5;
    const int wm   = wid >> 2;
    const int wn   = wid & 3;
    const int row0 = blockIdx.x * 128;
    const int r    = lane >> 2;
    const int c    = lane & 3;

    const int lrow  = tid >> 1;
    const int lhalf = tid & 1;

    float acc[4][4][4];
#pragma unroll
    for (int mt = 0; mt < 4; mt++)
#pragma unroll
        for (int nt = 0; nt < 4; nt++)
#pragma unroll
            for (int q = 0; q < 4; q++) acc[mt][nt][q] = 0.f;

    for (int kk = 0; kk < 16; kk++) {
        const int k0 = kk * 16;
        const float* A = (kk < 8) ? Aagg : Ah;
        const int ka = k0 & 127;

        {
            int gr = row0 + lrow;
            float vv[8];
            if (gr < n) {
                const float* ap = A + (size_t)gr * DD + ka + 8 * lhalf;
                float4 v0 = *(const float4*)ap;
                float4 v1 = *(const float4*)(ap + 4);
                vv[0]=v0.x; vv[1]=v0.y; vv[2]=v0.z; vv[3]=v0.w;
                vv[4]=v1.x; vv[5]=v1.y; vv[6]=v1.z; vv[7]=v1.w;
            } else {
#pragma unroll
                for (int j = 0; j < 8; j++) vv[j] = 0.f;
            }
#pragma unroll
            for (int j = 0; j < 4; j++) {
                float a0 = vv[2*j], a1 = vv[2*j+1];
                __nv_bfloat16 h0 = __float2bfloat16(a0);
                __nv_bfloat16 h1 = __float2bfloat16(a1);
                float l0 = a0 - __bfloat162float(h0);
                float l1 = a1 - __bfloat162float(h1);
                int w   = 4 * lhalf + j;
                int idx = lrow * 8 + (w ^ (lrow & 7));
                As_hi[idx] = pack_bf16(h0, h1);
                As_lo[idx] = pack_bf16(__float2bfloat16(l0), __float2bfloat16(l1));
            }
        }
        {
            const uint4 hv = *(const uint4*)(Whi + (size_t)lrow * 256 + k0 + 8 * lhalf);
            const uint4 lv = *(const uint4*)(Wlo + (size_t)lrow * 256 + k0 + 8 * lhalf);
            uint32_t hw[4] = {hv.x, hv.y, hv.z, hv.w};
            uint32_t lw[4] = {lv.x, lv.y, lv.z, lv.w};
#pragma unroll
            for (int j = 0; j < 4; j++) {
                int w   = 4 * lhalf + j;
                int idx = lrow * 8 + (w ^ (lrow & 7));
                Bs_hi[idx] = hw[j];
                Bs_lo[idx] = lw[j];
            }
        }
        __syncthreads();

        uint32_t afh[4][4], afl[4][4], bfh[4][2], bfl[4][2];
#pragma unroll
        for (int mt = 0; mt < 4; mt++) {
            int mr0 = wm * 64 + mt * 16 + r;
            int mr1 = mr0 + 8;
            afh[mt][0] = As_hi[mr0 * 8 + ( c      ^ (mr0 & 7))];
            afh[mt][1] = As_hi[mr1 * 8 + ( c      ^ (mr1 & 7))];
            afh[mt][2] = As_hi[mr0 * 8 + ((c + 4) ^ (mr0 & 7))];
            afh[mt][3] = As_hi[mr1 * 8 + ((c + 4) ^ (mr1 & 7))];
            afl[mt][0] = As_lo[mr0 * 8 + ( c      ^ (mr0 & 7))];
            afl[mt][1] = As_lo[mr1 * 8 + ( c      ^ (mr1 & 7))];
            afl[mt][2] = As_lo[mr0 * 8 + ((c + 4) ^ (mr0 & 7))];
            afl[mt][3] = As_lo[mr1 * 8 + ((c + 4) ^ (mr1 & 7))];
        }
#pragma unroll
        for (int nt = 0; nt < 4; nt++) {
            int nr = wn * 32 + nt * 8 + r;
            bfh[nt][0] = Bs_hi[nr * 8 + ( c      ^ (nr & 7))];
            bfh[nt][1] = Bs_hi[nr * 8 + ((c + 4) ^ (nr & 7))];
            bfl[nt][0] = Bs_lo[nr * 8 + ( c      ^ (nr & 7))];
            bfl[nt][1] = Bs_lo[nr * 8 + ((c + 4) ^ (nr & 7))];
        }

#pragma unroll
        for (int mt = 0; mt < 4; mt++)
#pragma unroll
            for (int nt = 0; nt < 4; nt++) {
                MMA_BF16(acc[mt][nt], afh[mt], bfh[nt]);
                MMA_BF16(acc[mt][nt], afh[mt], bfl[nt]);
                MMA_BF16(acc[mt][nt], afl[mt], bfh[nt]);
            }
        __syncthreads();
    }

#pragma unroll
    for (int nt = 0; nt < 4; nt++) {
        int col = wn * 32 + nt * 8 + 2 * c;
        float b0 = bias[col], b1 = bias[col + 1];
#pragma unroll
        for (int mt = 0; mt < 4; mt++) {
            int g0 = row0 + wm * 64 + mt * 16 + r;
            int g1 = g0 + 8;
            float v0 = acc[mt][nt][0] + b0;
            float v1 = acc[mt][nt][1] + b1;
            float v2 = acc[mt][nt][2] + b0;
            float v3 = acc[mt][nt][3] + b1;
            if (RELU) {
                v0 = fmaxf(v0, 0.f); v1 = fmaxf(v1, 0.f);
                v2 = fmaxf(v2, 0.f); v3 = fmaxf(v3, 0.f);
            }
            if (g0 < n) *(float2*)(out + (size_t)g0 * DD + col) = make_float2(v0, v1);
            if (g1 < n) *(float2*)(out + (size_t)g1 * DD + col) = make_float2(v2, v3);
        }
    }
}

// ---------------------------------------------------------------------------
// Launch
// ---------------------------------------------------------------------------
extern "C" void kernel_launch(void* const* d_in, const int* in_sizes, int n_in,
                              void* d_out, int out_size) {
    const float* x   = (const float*)d_in[0];
    const int*   ei  = (const int*)d_in[1];
    const float* ea  = (const float*)d_in[2];
    const float* wr[3] = {(const float*)d_in[3], (const float*)d_in[6], (const float*)d_in[9]};
    const float* br[3] = {(const float*)d_in[4], (const float*)d_in[7], (const float*)d_in[10]};
    const float* wo[3] = {(const float*)d_in[5], (const float*)d_in[8], (const float*)d_in[11]};
    float* out = (float*)d_out;

    const int n = in_sizes[0] / DD;   // 50000
    const int E = in_sizes[2];        // 800000

    float *buf0, *buf1, *agg, *ews;
    int *deg, *rowptr, *cursor, *esrc;
    __nv_bfloat16 *whi, *wlo;
    cudaGetSymbolAddress((void**)&buf0,   g_buf0);
    cudaGetSymbolAddress((void**)&buf1,   g_buf1);
    cudaGetSymbolAddress((void**)&agg,    g_agg);
    cudaGetSymbolAddress((void**)&whi,    g_whi);
    cudaGetSymbolAddress((void**)&wlo,    g_wlo);
    cudaGetSymbolAddress((void**)&deg,    g_deg);
    cudaGetSymbolAddress((void**)&rowptr, g_rowptr);
    cudaGetSymbolAddress((void**)&cursor, g_cursor);
    cudaGetSymbolAddress((void**)&esrc,   g_esrc);
    cudaGetSymbolAddress((void**)&ews,    g_ews);

    const int eb = (E + 255) / 256;
    const int nb = (n + 255) / 256;
    const int gb = (n + 127) / 128;
    const int pb = (DD * 256 + 255) / 256;
    const int wb = (n * 32 + 511) / 512;   // gather: 1 warp/node, 512 thr/blk

    // Weight prep
    for (int l = 0; l < 3; l++)
        prep_w<<<pb, 256>>>(wr[l], wo[l], whi + (size_t)l * DD * 256,
                            wlo + (size_t)l * DD * 256);

    // CSR build (once, reused by all layers)
    zero_deg<<<nb, 256>>>(deg, n);
    hist_kernel<<<eb, 256>>>(ei, deg, E);
    scan_kernel<<<1, 1024>>>(deg, rowptr, cursor, n);
    fill_kernel<<<eb, 256>>>(ei, ea, cursor, esrc, ews, E);

    // Layer 0
    gather_csr<<<wb, 512>>>(x, rowptr, esrc, ews, agg, n);
    gemm_mma<true><<<gb, 256>>>(agg, x, whi, wlo, br[0], buf0, n);
    // Layer 1
    gather_csr<<<wb, 512>>>(buf0, rowptr, esrc, ews, agg, n);
    gemm_mma<true><<<gb, 256>>>(agg, buf0, whi + (size_t)DD * 256,
                                wlo + (size_t)DD * 256, br[1], buf1, n);
    // Layer 2
    gather_csr<<<wb, 512>>>(buf1, rowptr, esrc, ews, agg, n);
    gemm_mma<false><<<gb, 256>>>(agg, buf1, whi + (size_t)2 * DD * 256,
                                 wlo + (size_t)2 * DD * 256, br[2], out, n);
}

// round 4
// speedup vs baseline: 2.6789x; 1.1615x over previous
#include <cuda_runtime.h>
#include <cuda_bf16.h>
#include <cstdint>
#include <cstddef>

#define NN 50000
#define EE 800000
#define DD 128
#define NLAYERS 3

// ---------------------------------------------------------------------------
// Scratch (device globals; allocation-free rule)
// ---------------------------------------------------------------------------
__device__ __nv_bfloat16 g_hA_hi[NN * DD], g_hA_lo[NN * DD];
__device__ __nv_bfloat16 g_hB_hi[NN * DD], g_hB_lo[NN * DD];
__device__ __nv_bfloat16 g_ag_hi[NN * DD], g_ag_lo[NN * DD];
__device__ __nv_bfloat16 g_whi[NLAYERS * DD * 256];
__device__ __nv_bfloat16 g_wlo[NLAYERS * DD * 256];
__device__ int   g_deg[NN];
__device__ int   g_rowptr[NN + 1];
__device__ int   g_cursor[NN];
__device__ int   g_esrc[EE];
__device__ float g_ews[EE];

__device__ __forceinline__ uint32_t pack_bf16(__nv_bfloat16 a, __nv_bfloat16 b) {
    __nv_bfloat162 t; t.x = a; t.y = b;
    return *reinterpret_cast<uint32_t*>(&t);
}
__device__ __forceinline__ float2 bf2f(uint32_t u) {
    __nv_bfloat162 b = *reinterpret_cast<__nv_bfloat162*>(&u);
    return __bfloat1622float2(b);
}

// ---------------------------------------------------------------------------
// CSR build
// ---------------------------------------------------------------------------
__global__ void zero_deg(int* __restrict__ deg, int n) {
    int i = blockIdx.x * blockDim.x + threadIdx.x;
    if (i < n) deg[i] = 0;
}

__global__ void hist_kernel(const int* __restrict__ ei, int* __restrict__ deg, int E) {
    int e = blockIdx.x * blockDim.x + threadIdx.x;
    if (e < E) atomicAdd(&deg[ei[E + e]], 1);
}

__global__ void __launch_bounds__(1024)
scan_kernel(const int* __restrict__ deg, int* __restrict__ rowptr,
            int* __restrict__ cursor, int n) {
    __shared__ int s[1024];
    const int t = threadIdx.x;
    const int C = (n + 1023) / 1024;
    const int beg = t * C;
    const int end = min(beg + C, n);
    int local = 0;
    for (int i = beg; i < end; i++) local += deg[i];
    s[t] = local;
    __syncthreads();
    for (int off = 1; off < 1024; off <<= 1) {
        int v = (t >= off) ? s[t - off] : 0;
        __syncthreads();
        s[t] += v;
        __syncthreads();
    }
    int run = s[t] - local;
    for (int i = beg; i < end; i++) {
        rowptr[i] = run;
        cursor[i] = run;
        run += deg[i];
    }
    if (t == 1023) rowptr[n] = s[1023];
}

__global__ void fill_kernel(const int* __restrict__ ei, const float* __restrict__ ew,
                            int* __restrict__ cursor,
                            int* __restrict__ esrc, float* __restrict__ ews, int E) {
    int e = blockIdx.x * blockDim.x + threadIdx.x;
    if (e >= E) return;
    int d = ei[E + e];
    int pos = atomicAdd(&cursor[d], 1);
    esrc[pos] = ei[e];
    ews[pos]  = ew[e];
}

// ---------------------------------------------------------------------------
// x -> bf16 hi/lo planes
// ---------------------------------------------------------------------------
__global__ void prep_x(const float* __restrict__ x,
                       __nv_bfloat16* __restrict__ hi, __nv_bfloat16* __restrict__ lo,
                       int n4) {
    int i = blockIdx.x * blockDim.x + threadIdx.x;
    if (i >= n4) return;
    float4 v = ((const float4*)x)[i];
    __nv_bfloat16 h0 = __float2bfloat16(v.x), h1 = __float2bfloat16(v.y);
    __nv_bfloat16 h2 = __float2bfloat16(v.z), h3 = __float2bfloat16(v.w);
    uint2 ho, lu;
    ho.x = pack_bf16(h0, h1);
    ho.y = pack_bf16(h2, h3);
    lu.x = pack_bf16(__float2bfloat16(v.x - __bfloat162float(h0)),
                     __float2bfloat16(v.y - __bfloat162float(h1)));
    lu.y = pack_bf16(__float2bfloat16(v.z - __bfloat162float(h2)),
                     __float2bfloat16(v.w - __bfloat162float(h3)));
    ((uint2*)hi)[i] = ho;
    ((uint2*)lo)[i] = lu;
}

// ---------------------------------------------------------------------------
// Weight prep: [Wrel; Wroot] transposed [n][k=256], bf16 hi/lo split.
// ---------------------------------------------------------------------------
__global__ void prep_w(const float* __restrict__ wrel,
                       const float* __restrict__ wroot,
                       __nv_bfloat16* __restrict__ whi,
                       __nv_bfloat16* __restrict__ wlo) {
    int i = blockIdx.x * blockDim.x + threadIdx.x;
    if (i >= DD * 256) return;
    int n = i >> 8;
    int k = i & 255;
    float v = (k < 128) ? wrel[k * DD + n] : wroot[(k - 128) * DD + n];
    __nv_bfloat16 h = __float2bfloat16(v);
    float lo = v - __bfloat162float(h);
    whi[n * 256 + k] = h;
    wlo[n * 256 + k] = __float2bfloat16(lo);
}

// ---------------------------------------------------------------------------
// Gather over CSR, bf16-plane I/O. One warp per node.
// ---------------------------------------------------------------------------
__global__ void __launch_bounds__(512)
gather_planes(const __nv_bfloat16* __restrict__ xhi, const __nv_bfloat16* __restrict__ xlo,
              const int* __restrict__ rowptr, const int* __restrict__ esrc,
              const float* __restrict__ ews,
              __nv_bfloat16* __restrict__ ahi, __nv_bfloat16* __restrict__ alo, int n) {
    int warp = (blockIdx.x * blockDim.x + threadIdx.x) >> 5;
    int lane = threadIdx.x & 31;
    if (warp >= n) return;
    int i   = rowptr[warp];
    int end = rowptr[warp + 1];
    const uint2* Hh = (const uint2*)xhi;
    const uint2* Hl = (const uint2*)xlo;
    float a0 = 0.f, a1 = 0.f, a2 = 0.f, a3 = 0.f;
    float b0 = 0.f, b1 = 0.f, b2 = 0.f, b3 = 0.f;
    for (; i + 1 < end; i += 2) {
        int   s0 = esrc[i],  s1 = esrc[i + 1];
        float w0 = ews[i],   w1 = ews[i + 1];
        uint2 h0 = __ldg(Hh + s0 * 32 + lane);
        uint2 l0 = __ldg(Hl + s0 * 32 + lane);
        uint2 h1 = __ldg(Hh + s1 * 32 + lane);
        uint2 l1 = __ldg(Hl + s1 * 32 + lane);
        float2 p, q;
        p = bf2f(h0.x); q = bf2f(l0.x); a0 += w0 * (p.x + q.x); a1 += w0 * (p.y + q.y);
        p = bf2f(h0.y); q = bf2f(l0.y); a2 += w0 * (p.x + q.x); a3 += w0 * (p.y + q.y);
        p = bf2f(h1.x); q = bf2f(l1.x); b0 += w1 * (p.x + q.x); b1 += w1 * (p.y + q.y);
        p = bf2f(h1.y); q = bf2f(l1.y); b2 += w1 * (p.x + q.x); b3 += w1 * (p.y + q.y);
    }
    if (i < end) {
        int   s0 = esrc[i];
        float w0 = ews[i];
        uint2 h0 = __ldg(Hh + s0 * 32 + lane);
        uint2 l0 = __ldg(Hl + s0 * 32 + lane);
        float2 p, q;
        p = bf2f(h0.x); q = bf2f(l0.x); a0 += w0 * (p.x + q.x); a1 += w0 * (p.y + q.y);
        p = bf2f(h0.y); q = bf2f(l0.y); a2 += w0 * (p.x + q.x); a3 += w0 * (p.y + q.y);
    }
    a0 += b0; a1 += b1; a2 += b2; a3 += b3;
    __nv_bfloat16 h0 = __float2bfloat16(a0), h1 = __float2bfloat16(a1);
    __nv_bfloat16 h2 = __float2bfloat16(a2), h3 = __float2bfloat16(a3);
    uint2 ho, lu;
    ho.x = pack_bf16(h0, h1);
    ho.y = pack_bf16(h2, h3);
    lu.x = pack_bf16(__float2bfloat16(a0 - __bfloat162float(h0)),
                     __float2bfloat16(a1 - __bfloat162float(h1)));
    lu.y = pack_bf16(__float2bfloat16(a2 - __bfloat162float(h2)),
                     __float2bfloat16(a3 - __bfloat162float(h3)));
    ((uint2*)ahi)[warp * 32 + lane] = ho;
    ((uint2*)alo)[warp * 32 + lane] = lu;
}

// ---------------------------------------------------------------------------
// GEMM: out = act( [agg|h] @ [Wrel;Wroot] + bias ), all operands bf16 hi/lo
// planes. cp.async double-buffered, BK=32, tile 128x128, 256 threads.
// Smem word layout per stage/plane: idx = row*16 + (w ^ (((row>>1)&3)<<2)).
// ---------------------------------------------------------------------------
#define MMA_BF16(acc, a, b)                                                    \
    asm volatile(                                                              \
        "mma.sync.aligned.m16n8k16.row.col.f32.bf16.bf16.f32 "                 \
        "{%0,%1,%2,%3}, {%4,%5,%6,%7}, {%8,%9}, {%0,%1,%2,%3};"                \
        : "+f"(acc[0]), "+f"(acc[1]), "+f"(acc[2]), "+f"(acc[3])               \
        : "r"(a[0]), "r"(a[1]), "r"(a[2]), "r"(a[3]), "r"(b[0]), "r"(b[1]))

#define CP16(dst, src, nbytes)                                                 \
    asm volatile("cp.async.cg.shared.global [%0], [%1], 16, %2;"               \
                 :: "r"(dst), "l"(src), "r"(nbytes))

__device__ __forceinline__ int sw_idx(int row, int w) {
    return row * 16 + (w ^ (((row >> 1) & 3) << 2));
}

template <bool RELU, bool PLANES>
__global__ void __launch_bounds__(256, 1)
gemm_mma(const __nv_bfloat16* __restrict__ Aghi, const __nv_bfloat16* __restrict__ Aglo,
         const __nv_bfloat16* __restrict__ Hhi,  const __nv_bfloat16* __restrict__ Hlo,
         const __nv_bfloat16* __restrict__ Whi,  const __nv_bfloat16* __restrict__ Wlo,
         const float* __restrict__ bias,
         float* __restrict__ outf,
         __nv_bfloat16* __restrict__ ohi, __nv_bfloat16* __restrict__ olo, int n) {
    extern __shared__ uint32_t smem[];   // 2 stages * 4 planes * 2048 words = 64KB

    const int tid  = threadIdx.x;
    const int lane = tid & 31;
    const int wid  = tid >> 5;
    const int wm   = wid >> 2;
    const int wn   = wid & 3;
    const int row0 = blockIdx.x * 128;
    const int r    = lane >> 2;
    const int c    = lane & 3;

    // loader mapping: thread -> (row, 2 chunks of 16B) per plane
    const int lrow = tid >> 1;
    const int j0   = (tid & 1) * 2;
    const int lq   = (lrow >> 1) & 3;
    const uint32_t sbase = (uint32_t)__cvta_generic_to_shared(smem);
    const int gr    = row0 + lrow;
    const uint32_t abytes = (gr < n) ? 16u : 0u;

    float acc[4][4][4];
#pragma unroll
    for (int mt = 0; mt < 4; mt++)
#pragma unroll
        for (int nt = 0; nt < 4; nt++)
#pragma unroll
            for (int q = 0; q < 4; q++) acc[mt][nt][q] = 0.f;

    // ---- stage loader ----
    auto load_stage = [&](int st, int kk) {
        const __nv_bfloat16* Ah = (kk < 4) ? Aghi : Hhi;
        const __nv_bfloat16* Al = (kk < 4) ? Aglo : Hlo;
        const int ka = (kk & 3) * 32;
        const int kb = kk * 32;
        const uint32_t stb = sbase + st * 32768;
#pragma unroll
        for (int jj = 0; jj < 2; jj++) {
            int j = j0 + jj;
            uint32_t doff = (uint32_t)(lrow * 64 + ((j ^ lq) << 4));
            const __nv_bfloat16* sa = Ah + (size_t)gr * DD + ka + j * 8;
            const __nv_bfloat16* sl = Al + (size_t)gr * DD + ka + j * 8;
            const __nv_bfloat16* sbh = Whi + (size_t)lrow * 256 + kb + j * 8;
            const __nv_bfloat16* sbl = Wlo + (size_t)lrow * 256 + kb + j * 8;
            CP16(stb + 0 * 8192 + doff, sa,  abytes);
            CP16(stb + 1 * 8192 + doff, sl,  abytes);
            CP16(stb + 2 * 8192 + doff, sbh, 16u);
            CP16(stb + 3 * 8192 + doff, sbl, 16u);
        }
        asm volatile("cp.async.commit_group;");
    };

    load_stage(0, 0);

    for (int kk = 0; kk < 8; kk++) {
        const int st = kk & 1;
        if (kk < 7) {
            load_stage(st ^ 1, kk + 1);
            asm volatile("cp.async.wait_group 1;");
        } else {
            asm volatile("cp.async.wait_group 0;");
        }
        __syncthreads();

        const uint32_t* Ahs = smem + st * 8192 + 0 * 2048;
        const uint32_t* Als = smem + st * 8192 + 1 * 2048;
        const uint32_t* Bhs = smem + st * 8192 + 2 * 2048;
        const uint32_t* Bls = smem + st * 8192 + 3 * 2048;

#pragma unroll
        for (int s = 0; s < 2; s++) {
            const int w0 = 8 * s + c;
            const int w1 = 8 * s + c + 4;
            uint32_t afh[4][4], afl[4][4], bfh[4][2], bfl[4][2];
#pragma unroll
            for (int mt = 0; mt < 4; mt++) {
                int mr0 = wm * 64 + mt * 16 + r;
                int mr1 = mr0 + 8;
                afh[mt][0] = Ahs[sw_idx(mr0, w0)];
                afh[mt][1] = Ahs[sw_idx(mr1, w0)];
                afh[mt][2] = Ahs[sw_idx(mr0, w1)];
                afh[mt][3] = Ahs[sw_idx(mr1, w1)];
                afl[mt][0] = Als[sw_idx(mr0, w0)];
                afl[mt][1] = Als[sw_idx(mr1, w0)];
                afl[mt][2] = Als[sw_idx(mr0, w1)];
                afl[mt][3] = Als[sw_idx(mr1, w1)];
            }
#pragma unroll
            for (int nt = 0; nt < 4; nt++) {
                int nr = wn * 32 + nt * 8 + r;
                bfh[nt][0] = Bhs[sw_idx(nr, w0)];
                bfh[nt][1] = Bhs[sw_idx(nr, w1)];
                bfl[nt][0] = Bls[sw_idx(nr, w0)];
                bfl[nt][1] = Bls[sw_idx(nr, w1)];
            }
#pragma unroll
            for (int mt = 0; mt < 4; mt++)
#pragma unroll
                for (int nt = 0; nt < 4; nt++) {
                    MMA_BF16(acc[mt][nt], afh[mt], bfh[nt]);
                    MMA_BF16(acc[mt][nt], afh[mt], bfl[nt]);
                    MMA_BF16(acc[mt][nt], afl[mt], bfh[nt]);
                }
        }
        __syncthreads();
    }

    // ---- epilogue ----
#pragma unroll
    for (int nt = 0; nt < 4; nt++) {
        int col = wn * 32 + nt * 8 + 2 * c;
        float b0 = bias[col], b1 = bias[col + 1];
#pragma unroll
        for (int mt = 0; mt < 4; mt++) {
            int g0 = row0 + wm * 64 + mt * 16 + r;
            int g1 = g0 + 8;
            float v0 = acc[mt][nt][0] + b0;
            float v1 = acc[mt][nt][1] + b1;
            float v2 = acc[mt][nt][2] + b0;
            float v3 = acc[mt][nt][3] + b1;
            if (RELU) {
                v0 = fmaxf(v0, 0.f); v1 = fmaxf(v1, 0.f);
                v2 = fmaxf(v2, 0.f); v3 = fmaxf(v3, 0.f);
            }
            if (PLANES) {
                if (g0 < n) {
                    __nv_bfloat16 h0 = __float2bfloat16(v0), h1 = __float2bfloat16(v1);
                    *(uint32_t*)(ohi + (size_t)g0 * DD + col) = pack_bf16(h0, h1);
                    *(uint32_t*)(olo + (size_t)g0 * DD + col) =
                        pack_bf16(__float2bfloat16(v0 - __bfloat162float(h0)),
                                  __float2bfloat16(v1 - __bfloat162float(h1)));
                }
                if (g1 < n) {
                    __nv_bfloat16 h2 = __float2bfloat16(v2), h3 = __float2bfloat16(v3);
                    *(uint32_t*)(ohi + (size_t)g1 * DD + col) = pack_bf16(h2, h3);
                    *(uint32_t*)(olo + (size_t)g1 * DD + col) =
                        pack_bf16(__float2bfloat16(v2 - __bfloat162float(h2)),
                                  __float2bfloat16(v3 - __bfloat162float(h3)));
                }
            } else {
                if (g0 < n) *(float2*)(outf + (size_t)g0 * DD + col) = make_float2(v0, v1);
                if (g1 < n) *(float2*)(outf + (size_t)g1 * DD + col) = make_float2(v2, v3);
            }
        }
    }
}

// ---------------------------------------------------------------------------
// Launch
// ---------------------------------------------------------------------------
extern "C" void kernel_launch(void* const* d_in, const int* in_sizes, int n_in,
                              void* d_out, int out_size) {
    const float* x   = (const float*)d_in[0];
    const int*   ei  = (const int*)d_in[1];
    const float* ea  = (const float*)d_in[2];
    const float* wr[3] = {(const float*)d_in[3], (const float*)d_in[6], (const float*)d_in[9]};
    const float* br[3] = {(const float*)d_in[4], (const float*)d_in[7], (const float*)d_in[10]};
    const float* wo[3] = {(const float*)d_in[5], (const float*)d_in[8], (const float*)d_in[11]};
    float* out = (float*)d_out;

    const int n = in_sizes[0] / DD;   // 50000
    const int E = in_sizes[2];        // 800000

    __nv_bfloat16 *hAh, *hAl, *hBh, *hBl, *agh, *agl, *whi, *wlo;
    int *deg, *rowptr, *cursor, *esrc;
    float *ews;
    cudaGetSymbolAddress((void**)&hAh,    g_hA_hi);
    cudaGetSymbolAddress((void**)&hAl,    g_hA_lo);
    cudaGetSymbolAddress((void**)&hBh,    g_hB_hi);
    cudaGetSymbolAddress((void**)&hBl,    g_hB_lo);
    cudaGetSymbolAddress((void**)&agh,    g_ag_hi);
    cudaGetSymbolAddress((void**)&agl,    g_ag_lo);
    cudaGetSymbolAddress((void**)&whi,    g_whi);
    cudaGetSymbolAddress((void**)&wlo,    g_wlo);
    cudaGetSymbolAddress((void**)&deg,    g_deg);
    cudaGetSymbolAddress((void**)&rowptr, g_rowptr);
    cudaGetSymbolAddress((void**)&cursor, g_cursor);
    cudaGetSymbolAddress((void**)&esrc,   g_esrc);
    cudaGetSymbolAddress((void**)&ews,    g_ews);

    static bool attr_done = false;
    // cudaFuncSetAttribute is idempotent; calling every time keeps determinism.
    cudaFuncSetAttribute(gemm_mma<true, true>,
                         cudaFuncAttributeMaxDynamicSharedMemorySize, 65536);
    cudaFuncSetAttribute(gemm_mma<false, false>,
                         cudaFuncAttributeMaxDynamicSharedMemorySize, 65536);
    (void)attr_done;

    const int eb = (E + 255) / 256;
    const int nb = (n + 255) / 256;
    const int gb = (n + 127) / 128;
    const int pb = (DD * 256 + 255) / 256;
    const int xb = (n * DD / 4 + 255) / 256;
    const int wb = (n * 32 + 511) / 512;

    // CSR build
    zero_deg<<<nb, 256>>>(deg, n);
    hist_kernel<<<eb, 256>>>(ei, deg, E);
    scan_kernel<<<1, 1024>>>(deg, rowptr, cursor, n);
    fill_kernel<<<eb, 256>>>(ei, ea, cursor, esrc, ews, E);

    // Feature / weight prep
    prep_x<<<xb, 256>>>(x, hAh, hAl, n * DD / 4);
    for (int l = 0; l < 3; l++)
        prep_w<<<pb, 256>>>(wr[l], wo[l], whi + (size_t)l * DD * 256,
                            wlo + (size_t)l * DD * 256);

    // Layer 0: hA -> hB (relu)
    gather_planes<<<wb, 512>>>(hAh, hAl, rowptr, esrc, ews, agh, agl, n);
    gemm_mma<true, true><<<gb, 256, 65536>>>(agh, agl, hAh, hAl, whi, wlo,
                                             br[0], nullptr, hBh, hBl, n);
    // Layer 1: hB -> hA (relu)
    gather_planes<<<wb, 512>>>(hBh, hBl, rowptr, esrc, ews, agh, agl, n);
    gemm_mma<true, true><<<gb, 256, 65536>>>(agh, agl, hBh, hBl,
                                             whi + (size_t)DD * 256, wlo + (size_t)DD * 256,
                                             br[1], nullptr, hAh, hAl, n);
    // Layer 2: hA -> out (fp32, no relu)
    gather_planes<<<wb, 512>>>(hAh, hAl, rowptr, esrc, ews, agh, agl, n);
    gemm_mma<false, false><<<gb, 256, 65536>>>(agh, agl, hAh, hAl,
                                               whi + (size_t)2 * DD * 256, wlo + (size_t)2 * DD * 256,
                                               br[2], out, nullptr, nullptr, n);
}